// round 14
// baseline (speedup 1.0000x reference)
#include <cuda_runtime.h>

#define BB 4
#define HH 480
#define WW 640
#define HWp (HH * WW)
#define NPIX (BB * HWp)
#define PADX 8
#define PW (WW + 2 * PADX)      /* 656, padded row stride */
#define PHW (HH * PW)           /* per-batch padded plane size */

// Scratch (static __device__ arrays — no allocation; zero-initialized)
__device__ float  g_aff[9 * NPIX];    // normalized affinities, plane layout
__device__ float2 g_off[8 * NPIX];    // packed (dy,dx) per tap, plane layout
__device__ float  g_wA [NPIX];        // (1-m)*confidence
__device__ __align__(16) float g_pingA [BB * PHW];   // g state, x-padded
__device__ __align__(16) float g_pongA [BB * PHW];
__device__ __align__(16) float gS_pingA[BB * PHW];   // shifted copy: gS[k] = g[k+1]
__device__ __align__(16) float gS_pongA[BB * PHW];

// ---------------------------------------------------------------------------
// Pass A: affinity normalization (tanh once) + offset packing + wA + initial g
// (writes both padded g and shifted copy gS)
// ---------------------------------------------------------------------------
__global__ void __launch_bounds__(256)
precompute_kernel(const float* __restrict__ feat_init,
                  const float* __restrict__ guidance,
                  const float* __restrict__ confidence,
                  const float* __restrict__ feat_fix,
                  const float* __restrict__ aff_scale) {
    int idx = blockIdx.x * blockDim.x + threadIdx.x;
    if (idx >= NPIX) return;
    int b = idx / HWp;
    int p = idx - b * HWp;
    int y = p / WW;
    int x = p - y * WW;

    const float* gbase = guidance + (size_t)b * 24 * HWp + p;

    // pack offsets: tap t <-> guidance channels (2t, 2t+1)
#pragma unroll
    for (int t = 0; t < 8; t++) {
        float dy = gbase[(size_t)(2 * t) * HWp];
        float dx = gbase[(size_t)(2 * t + 1) * HWp];
        g_off[(size_t)(b * 8 + t) * HWp + p] = make_float2(dy, dx);
    }

    // affinity normalization (fp32 throughout, exact)
    const float* gp = gbase + (size_t)16 * HWp;
    float scale = aff_scale[0] + 1e-8f;
    float a[8];
    float s = 1e-4f;
#pragma unroll
    for (int j = 0; j < 8; j++) {
        a[j] = tanhf(gp[(size_t)j * HWp]) / scale;
        s += fabsf(a[j]);
    }
    s = fmaxf(s, 1.0f);
    float inv = 1.0f / s;
    float sum = 0.0f;
#pragma unroll
    for (int j = 0; j < 8; j++) { a[j] *= inv; sum += a[j]; }
    float aref = 1.0f - sum;

    float* ap = g_aff + (size_t)b * 9 * HWp + p;
#pragma unroll
    for (int j = 0; j < 4; j++) ap[(size_t)j * HWp] = a[j];
    ap[(size_t)4 * HWp] = aref;
#pragma unroll
    for (int j = 4; j < 8; j++) ap[(size_t)(j + 1) * HWp] = a[j];

    // wA = (1-m)*conf ; initial g = feat * conf
    float ff = feat_fix[idx];
    float fi = feat_init[idx];
    float cf = confidence[idx];
    bool m = ff > 0.0f;
    float conf = m ? 1.0f : cf;
    float feat = m ? ff : fi;
    g_wA[idx]  = m ? 0.0f : cf;

    float gval = feat * conf;
    size_t pb = (size_t)b * PHW + (size_t)y * PW + PADX;
    g_pingA[pb + x] = gval;
    gS_pingA[pb + x - 1] = gval;     // gS[x-1] = g[x]; x=0 lands in pad (valid slot)
}

// ---------------------------------------------------------------------------
// Propagation step, 4 pixels per thread, pair-gathers via shifted copy.
//   g_out = wA * (sum_t aff_t * bilinear(g_in, pos_t) + aff_c * g_in) + ff
// last==1: wA -> (1-m); writes unpadded d_out, skips gS maintenance.
// ---------------------------------------------------------------------------
__global__ void __launch_bounds__(256, 3)
prop_kernel(const float* __restrict__ ffix,
            const float* __restrict__ gin,
            const float* __restrict__ gSin,
            float* __restrict__ gout,
            float* __restrict__ gSout,
            float* __restrict__ finalout,
            int last, int b0) {
    int t4 = (blockIdx.x * blockDim.x + threadIdx.x) * 4;
    if (t4 >= 2 * HWp) return;
    int brel = t4 / HWp;
    int b = b0 + brel;
    int p = t4 - brel * HWp;         // multiple of 4; 4 pixels same row
    int y = p / WW;
    int x = p - y * WW;              // multiple of 4

    const float2* offp = g_off + (size_t)b * 8 * HWp + p;
    const float*  affp = g_aff + (size_t)b * 9 * HWp + p;
    const float*  gb   = gin  + (size_t)b * PHW + PADX;   // element e at gb[row*PW + e]
    const float*  gSb  = gSin + (size_t)b * PHW + PADX;

    const int kyv[8] = {-1, -1, -1, 0, 0, 1, 1, 1};
    const int kxv[8] = {-1, 0, 1, -1, 1, -1, 0, 1};

    float acc0 = 0.0f, acc1 = 0.0f, acc2 = 0.0f, acc3 = 0.0f;

#pragma unroll
    for (int t = 0; t < 8; t++) {
        const float* op = (const float*)(offp + (size_t)t * HWp);
        float4 oA = *reinterpret_cast<const float4*>(op);       // (dy0,dx0,dy1,dx1)
        float4 oB = *reinterpret_cast<const float4*>(op + 4);   // (dy2,dx2,dy3,dx3)
        int j = (t < 4) ? t : (t + 1);
        float4 av = *reinterpret_cast<const float4*>(affp + (size_t)j * HWp);

        float dys[4] = {oA.x, oA.z, oB.x, oB.z};
        float dxs[4] = {oA.y, oA.w, oB.y, oB.w};
        float afs[4] = {av.x, av.y, av.z, av.w};
        float* accs[4] = {&acc0, &acc1, &acc2, &acc3};

#pragma unroll
        for (int q = 0; q < 4; q++) {
            float py = (float)(y + kyv[t]) + dys[q];
            float px = (float)(x + q + kxv[t]) + dxs[q];
            float y0f = floorf(py);
            float x0f = floorf(px);
            int y0 = (int)y0f;
            int x0 = (int)x0f;
            float wy = py - y0f;
            float wx = px - x0f;

            bool vy0 = (unsigned)y0 < (unsigned)HH;
            bool vy1 = (unsigned)(y0 + 1) < (unsigned)HH;
            bool vx0 = (unsigned)x0 < (unsigned)WW;
            bool vx1 = (unsigned)(x0 + 1) < (unsigned)WW;

            float w00 = (1.0f - wy) * (1.0f - wx);
            float w01 = (1.0f - wy) * wx;
            float w10 = wy * (1.0f - wx);
            float w11 = wy * wx;
            w00 = (vy0 && vx0) ? w00 : 0.0f;
            w01 = (vy0 && vx1) ? w01 : 0.0f;
            w10 = (vy1 && vx0) ? w10 : 0.0f;
            w11 = (vy1 && vx1) ? w11 : 0.0f;

            int cy0 = min(max(y0, 0), HH - 1);
            int cy1 = min(max(y0 + 1, 0), HH - 1);
            // pair (x0, x0+1): one aligned float2 from g (x0 even) or gS (x0 odd)
            int cxc = min(max(x0, -PADX), WW + PADX - 2);  // [-8, 646]
            const float* arr = (cxc & 1) ? gSb : gb;
            int kx = cxc & ~1;                              // even, >= -8

            float2 r0 = *reinterpret_cast<const float2*>(arr + (size_t)cy0 * PW + kx);
            float2 r1 = *reinterpret_cast<const float2*>(arr + (size_t)cy1 * PW + kx);

            float samp = w00 * r0.x;
            samp = fmaf(w01, r0.y, samp);
            samp = fmaf(w10, r1.x, samp);
            samp = fmaf(w11, r1.y, samp);

            *accs[q] = fmaf(afs[q], samp, *accs[q]);
        }
    }

    // center tap: offset exactly zero -> sample = g[p..p+3]
    {
        float4 ac = *reinterpret_cast<const float4*>(affp + (size_t)4 * HWp);
        float4 gc = *reinterpret_cast<const float4*>(gb + (size_t)y * PW + x);
        acc0 = fmaf(ac.x, gc.x, acc0);
        acc1 = fmaf(ac.y, gc.y, acc1);
        acc2 = fmaf(ac.z, gc.z, acc2);
        acc3 = fmaf(ac.w, gc.w, acc3);
    }

    int gidx = b * HWp + p;
    float4 ffv = *reinterpret_cast<const float4*>(ffix + gidx);
    float4 w;
    if (last) {
        w.x = (ffv.x > 0.0f) ? 0.0f : 1.0f;
        w.y = (ffv.y > 0.0f) ? 0.0f : 1.0f;
        w.z = (ffv.z > 0.0f) ? 0.0f : 1.0f;
        w.w = (ffv.w > 0.0f) ? 0.0f : 1.0f;
    } else {
        w = *reinterpret_cast<const float4*>(g_wA + gidx);
    }

    float r0 = fmaf(w.x, acc0, ffv.x);
    float r1 = fmaf(w.y, acc1, ffv.y);
    float r2 = fmaf(w.z, acc2, ffv.z);
    float r3 = fmaf(w.w, acc3, ffv.w);

    if (last) {
        *reinterpret_cast<float4*>(finalout + gidx) = make_float4(r0, r1, r2, r3);
    } else {
        float* go  = gout  + (size_t)b * PHW + (size_t)y * PW + PADX;
        float* gSo = gSout + (size_t)b * PHW + (size_t)y * PW + PADX;
        *reinterpret_cast<float4*>(go + x) = make_float4(r0, r1, r2, r3);
        // shifted copy: gS[k] = g[k+1] (row-local; x-1 at row start lands in pad slot)
        gSo[x - 1] = r0;
        *reinterpret_cast<float2*>(gSo + x) = make_float2(r1, r2);
        gSo[x + 2] = r3;
    }
}

// ---------------------------------------------------------------------------
extern "C" void kernel_launch(void* const* d_in, const int* in_sizes, int n_in,
                              void* d_out, int out_size) {
    const float* feat_init  = (const float*)d_in[0];
    const float* guidance   = (const float*)d_in[1];
    const float* confidence = (const float*)d_in[2];
    const float* feat_fix   = (const float*)d_in[3];
    const float* aff_scale  = (const float*)d_in[4];
    float* out = (float*)d_out;

    float *gp = nullptr, *gq = nullptr, *sp = nullptr, *sq = nullptr;
    cudaGetSymbolAddress((void**)&gp, g_pingA);
    cudaGetSymbolAddress((void**)&gq, g_pongA);
    cudaGetSymbolAddress((void**)&sp, gS_pingA);
    cudaGetSymbolAddress((void**)&sq, gS_pongA);

    const int threads = 256;
    const int blocksA = (NPIX + threads - 1) / threads;
    const int blocksP = (2 * HWp / 4 + threads - 1) / threads;   // 600

    precompute_kernel<<<blocksA, threads>>>(feat_init, guidance, confidence,
                                            feat_fix, aff_scale);

    // Batch groups {0,1} then {2,3}
    for (int b0 = 0; b0 < BB; b0 += 2) {
        float *gcur = gp, *gnxt = gq, *scur = sp, *snxt = sq;
        for (int i = 1; i <= 17; i++) {
            prop_kernel<<<blocksP, threads>>>(feat_fix, gcur, scur,
                                              gnxt, snxt, nullptr,
                                              /*last=*/0, b0);
            float* t;
            t = gcur; gcur = gnxt; gnxt = t;
            t = scur; scur = snxt; snxt = t;
        }
        prop_kernel<<<blocksP, threads>>>(feat_fix, gcur, scur,
                                          nullptr, nullptr, out,
                                          /*last=*/1, b0);
    }
}

// round 16
// speedup vs baseline: 1.0613x; 1.0613x over previous
#include <cuda_runtime.h>

#define BB 4
#define HH 480
#define WW 640
#define HWp (HH * WW)
#define NPIX (BB * HWp)

// Padded state plane: 8-px zero ring on all sides (never written -> stays 0)
#define PADX 8
#define PADY 8
#define PW (WW + 2 * PADX)          /* 656 */
#define PH (HH + 2 * PADY)          /* 496 */
#define PHW (PH * PW)               /* per-batch padded plane */

// Scratch (static __device__ arrays — zero-initialized at module load)
__device__ float  g_aff[9 * NPIX];    // normalized affinities, plane layout
__device__ float2 g_off[8 * NPIX];    // packed (dy,dx) per tap, plane layout
__device__ float  g_wA [NPIX];        // (1-m)*confidence
__device__ float  g_pingA[BB * PHW];  // padded g state (ring always zero)
__device__ float  g_pongA[BB * PHW];

// ---------------------------------------------------------------------------
// Pass A: affinity normalization (tanh once) + offset packing + wA + initial g
// ---------------------------------------------------------------------------
__global__ void __launch_bounds__(256)
precompute_kernel(const float* __restrict__ feat_init,
                  const float* __restrict__ guidance,
                  const float* __restrict__ confidence,
                  const float* __restrict__ feat_fix,
                  const float* __restrict__ aff_scale) {
    int idx = blockIdx.x * blockDim.x + threadIdx.x;
    if (idx >= NPIX) return;
    int b = idx / HWp;
    int p = idx - b * HWp;
    int y = p / WW;
    int x = p - y * WW;

    const float* gbase = guidance + (size_t)b * 24 * HWp + p;

    // pack offsets: tap t <-> guidance channels (2t, 2t+1)
#pragma unroll
    for (int t = 0; t < 8; t++) {
        float dy = gbase[(size_t)(2 * t) * HWp];
        float dx = gbase[(size_t)(2 * t + 1) * HWp];
        g_off[(size_t)(b * 8 + t) * HWp + p] = make_float2(dy, dx);
    }

    // affinity normalization (fp32 throughout, exact)
    const float* gp = gbase + (size_t)16 * HWp;
    float scale = aff_scale[0] + 1e-8f;
    float a[8];
    float s = 1e-4f;
#pragma unroll
    for (int j = 0; j < 8; j++) {
        a[j] = tanhf(gp[(size_t)j * HWp]) / scale;
        s += fabsf(a[j]);
    }
    s = fmaxf(s, 1.0f);
    float inv = 1.0f / s;
    float sum = 0.0f;
#pragma unroll
    for (int j = 0; j < 8; j++) { a[j] *= inv; sum += a[j]; }
    float aref = 1.0f - sum;

    float* ap = g_aff + (size_t)b * 9 * HWp + p;
#pragma unroll
    for (int j = 0; j < 4; j++) ap[(size_t)j * HWp] = a[j];
    ap[(size_t)4 * HWp] = aref;
#pragma unroll
    for (int j = 4; j < 8; j++) ap[(size_t)(j + 1) * HWp] = a[j];

    // wA = (1-m)*conf ; initial g = feat * conf
    float ff = feat_fix[idx];
    float fi = feat_init[idx];
    float cf = confidence[idx];
    bool m = ff > 0.0f;
    float conf = m ? 1.0f : cf;
    float feat = m ? ff : fi;
    g_wA[idx]  = m ? 0.0f : cf;

    // write interior of padded plane only (ring stays zero forever)
    g_pingA[(size_t)b * PHW + (size_t)(y + PADY) * PW + (x + PADX)] = feat * conf;
}

// ---------------------------------------------------------------------------
// Bilinear from padded plane: no masks, no selects — ring zeros implement the
// zero-outside semantics. gb points at (0,0) interior; valid index range
// covers y0 in [-PADY, HH+PADY-2], x0 in [-PADX, WW+PADX-2].
// ---------------------------------------------------------------------------
__device__ __forceinline__ float bil_pad(const float* __restrict__ gb,
                                         float py, float px) {
    float y0f = floorf(py);
    float x0f = floorf(px);
    float wy = py - y0f;
    float wx = px - x0f;
    int y0 = min(max((int)y0f, -PADY), HH + PADY - 2);
    int x0 = min(max((int)x0f, -PADX), WW + PADX - 2);

    const float* c = gb + (size_t)y0 * PW + x0;
    float v00 = c[0];
    float v01 = c[1];
    float v10 = c[PW];
    float v11 = c[PW + 1];

    float top = fmaf(wx, v01 - v00, v00);
    float bot = fmaf(wx, v11 - v10, v10);
    return fmaf(wy, bot - top, top);
}

// ---------------------------------------------------------------------------
// Propagation step over batch group [b0, b0+2), 2 pixels per thread:
//   g_out = wA * (sum_t aff_t * bilinear(g_in, pos_t) + aff_c * g_in[p]) + ff
// last==1: wA -> (1-m); writes unpadded d_out.
// ---------------------------------------------------------------------------
__global__ void __launch_bounds__(256)
prop_kernel(const float* __restrict__ feat_fix,
            const float* __restrict__ gin,
            float* __restrict__ gout,
            float* __restrict__ finalout,
            int last, int b0) {
    int pair = blockIdx.x * blockDim.x + threadIdx.x;
    int base2 = pair * 2;                 // index within the 2-batch group
    if (base2 >= 2 * HWp) return;
    int brel = base2 / HWp;
    int b = b0 + brel;
    int p = base2 - brel * HWp;           // even; both pixels same batch
    int gidx = b * HWp + p;

    int y0r = p / WW;
    int x0r = p - y0r * WW;
    int x1r = x0r + 1;
    int y1r = y0r;
    if (x1r == WW) { x1r = 0; y1r++; }

    const float2* offp = g_off + (size_t)b * 8 * HWp + p;
    const float*  affp = g_aff + (size_t)b * 9 * HWp + p;
    // interior (0,0) of this batch's padded plane
    const float*  gb = gin + (size_t)b * PHW + (size_t)PADY * PW + PADX;

    // front-batch all offset loads (one float4 per tap covers both pixels)
    float4 o[8];
#pragma unroll
    for (int t = 0; t < 8; t++)
        o[t] = *reinterpret_cast<const float4*>(offp + (size_t)t * HWp);

    const int kyv[8] = {-1, -1, -1, 0, 0, 1, 1, 1};
    const int kxv[8] = {-1, 0, 1, -1, 1, -1, 0, 1};

    float acc0 = 0.0f, acc1 = 0.0f;

#pragma unroll
    for (int t = 0; t < 8; t++) {
        int j = (t < 4) ? t : (t + 1);   // affinity plane index
        float2 a = *reinterpret_cast<const float2*>(affp + (size_t)j * HWp);

        float s0 = bil_pad(gb, (float)(y0r + kyv[t]) + o[t].x,
                               (float)(x0r + kxv[t]) + o[t].y);
        float s1 = bil_pad(gb, (float)(y1r + kyv[t]) + o[t].z,
                               (float)(x1r + kxv[t]) + o[t].w);
        acc0 = fmaf(a.x, s0, acc0);
        acc1 = fmaf(a.y, s1, acc1);
    }

    // center tap: offset exactly zero -> sample = g[p] (direct reads)
    {
        float2 ac = *reinterpret_cast<const float2*>(affp + (size_t)4 * HWp);
        float gc0 = gb[(size_t)y0r * PW + x0r];
        float gc1 = gb[(size_t)y1r * PW + x1r];
        acc0 = fmaf(ac.x, gc0, acc0);
        acc1 = fmaf(ac.y, gc1, acc1);
    }

    float2 ffv = *reinterpret_cast<const float2*>(feat_fix + gidx);
    float2 w;
    if (last) {
        w.x = (ffv.x > 0.0f) ? 0.0f : 1.0f;
        w.y = (ffv.y > 0.0f) ? 0.0f : 1.0f;
    } else {
        w = *reinterpret_cast<const float2*>(g_wA + gidx);
    }

    float r0 = fmaf(w.x, acc0, ffv.x);
    float r1 = fmaf(w.y, acc1, ffv.y);

    if (last) {
        *reinterpret_cast<float2*>(finalout + gidx) = make_float2(r0, r1);
    } else {
        // interior writes only — zero ring untouched
        float* go = gout + (size_t)b * PHW;
        go[(size_t)(y0r + PADY) * PW + (x0r + PADX)] = r0;
        go[(size_t)(y1r + PADY) * PW + (x1r + PADX)] = r1;
    }
}

// ---------------------------------------------------------------------------
extern "C" void kernel_launch(void* const* d_in, const int* in_sizes, int n_in,
                              void* d_out, int out_size) {
    const float* feat_init  = (const float*)d_in[0];
    const float* guidance   = (const float*)d_in[1];
    const float* confidence = (const float*)d_in[2];
    const float* feat_fix   = (const float*)d_in[3];
    const float* aff_scale  = (const float*)d_in[4];
    float* out = (float*)d_out;

    float *gp = nullptr, *gq = nullptr;
    cudaGetSymbolAddress((void**)&gp, g_pingA);
    cudaGetSymbolAddress((void**)&gq, g_pongA);

    const int threads = 256;
    const int blocksA = (NPIX + threads - 1) / threads;
    const int blocksP = (2 * HWp / 2 + threads - 1) / threads;   // 1200

    precompute_kernel<<<blocksA, threads>>>(feat_init, guidance, confidence,
                                            feat_fix, aff_scale);

    // Batch groups {0,1} then {2,3}
    for (int b0 = 0; b0 < BB; b0 += 2) {
        float *cur = gp, *nxt = gq;
        for (int i = 1; i <= 17; i++) {
            prop_kernel<<<blocksP, threads>>>(feat_fix, cur, nxt, nullptr,
                                              /*last=*/0, b0);
            float* t = cur; cur = nxt; nxt = t;
        }
        prop_kernel<<<blocksP, threads>>>(feat_fix, cur, nullptr, out,
                                          /*last=*/1, b0);
    }
}

// round 17
// speedup vs baseline: 1.1658x; 1.0984x over previous
#include <cuda_runtime.h>

#define BB 4
#define HH 480
#define WW 640
#define HWp (HH * WW)
#define NPIX (BB * HWp)

// Padded state plane: 8-px zero ring on all sides (never written -> stays 0)
#define PADX 8
#define PADY 8
#define PW (WW + 2 * PADX)          /* 656 */
#define PH (HH + 2 * PADY)          /* 496 */
#define PHW (PH * PW)               /* per-batch padded plane */

// Scratch (static __device__ arrays — zero-initialized at module load)
__device__ float  g_aff[9 * NPIX];    // normalized affinities, plane layout
__device__ float2 g_off[8 * NPIX];    // packed (dy,dx) per tap, plane layout
__device__ float  g_wA [NPIX];        // (1-m)*confidence
__device__ __align__(16) float g_pingA [BB * PHW];  // padded g state
__device__ __align__(16) float g_pongA [BB * PHW];
__device__ __align__(16) float gS_pingA[BB * PHW];  // shifted: gS[k] = g[k+1]
__device__ __align__(16) float gS_pongA[BB * PHW];

// ---------------------------------------------------------------------------
// Pass A: affinity normalization (tanh once) + offset packing + wA + initial g
// ---------------------------------------------------------------------------
__global__ void __launch_bounds__(256)
precompute_kernel(const float* __restrict__ feat_init,
                  const float* __restrict__ guidance,
                  const float* __restrict__ confidence,
                  const float* __restrict__ feat_fix,
                  const float* __restrict__ aff_scale) {
    int idx = blockIdx.x * blockDim.x + threadIdx.x;
    if (idx >= NPIX) return;
    int b = idx / HWp;
    int p = idx - b * HWp;
    int y = p / WW;
    int x = p - y * WW;

    const float* gbase = guidance + (size_t)b * 24 * HWp + p;

    // pack offsets: tap t <-> guidance channels (2t, 2t+1)
#pragma unroll
    for (int t = 0; t < 8; t++) {
        float dy = gbase[(size_t)(2 * t) * HWp];
        float dx = gbase[(size_t)(2 * t + 1) * HWp];
        g_off[(size_t)(b * 8 + t) * HWp + p] = make_float2(dy, dx);
    }

    // affinity normalization (fp32 throughout, exact)
    const float* gp = gbase + (size_t)16 * HWp;
    float scale = aff_scale[0] + 1e-8f;
    float a[8];
    float s = 1e-4f;
#pragma unroll
    for (int j = 0; j < 8; j++) {
        a[j] = tanhf(gp[(size_t)j * HWp]) / scale;
        s += fabsf(a[j]);
    }
    s = fmaxf(s, 1.0f);
    float inv = 1.0f / s;
    float sum = 0.0f;
#pragma unroll
    for (int j = 0; j < 8; j++) { a[j] *= inv; sum += a[j]; }
    float aref = 1.0f - sum;

    float* ap = g_aff + (size_t)b * 9 * HWp + p;
#pragma unroll
    for (int j = 0; j < 4; j++) ap[(size_t)j * HWp] = a[j];
    ap[(size_t)4 * HWp] = aref;
#pragma unroll
    for (int j = 4; j < 8; j++) ap[(size_t)(j + 1) * HWp] = a[j];

    // wA = (1-m)*conf ; initial g = feat * conf
    float ff = feat_fix[idx];
    float fi = feat_init[idx];
    float cf = confidence[idx];
    bool m = ff > 0.0f;
    float conf = m ? 1.0f : cf;
    float feat = m ? ff : fi;
    g_wA[idx]  = m ? 0.0f : cf;

    float gval = feat * conf;
    size_t pb = (size_t)b * PHW + (size_t)(y + PADY) * PW + PADX;
    g_pingA [pb + x]     = gval;
    gS_pingA[pb + x - 1] = gval;   // gS[k] = g[k+1]; x=0 writes pad slot (exists)
}

// ---------------------------------------------------------------------------
// Bilinear via pair-gathers. gb/gSb point at interior (0,0). Ring zeros give
// exact zero-outside semantics; clamp only guards the ring (beyond it the
// sample is exactly 0 anyway since weights pick ring values).
// One aligned LDG.64 per corner-row: pair (x0, x0+1) from g (x0 even) or
// gS (x0 odd, gS[k]=g[k+1]).
// ---------------------------------------------------------------------------
__device__ __forceinline__ float bil_pair(const float* __restrict__ gb,
                                          const float* __restrict__ gSb,
                                          float py, float px) {
    float y0f = floorf(py);
    float x0f = floorf(px);
    float wy = py - y0f;
    float wx = px - x0f;
    int y0 = min(max((int)y0f, -PADY), HH + PADY - 2);
    int x0 = min(max((int)x0f, -PADX), WW + PADX - 2);

    const float* arr = (x0 & 1) ? gSb : gb;
    int kx = x0 & ~1;              // even, >= -8  (8B-aligned interior offset)

    const float* c = arr + (size_t)y0 * PW + kx;
    float2 r0 = *reinterpret_cast<const float2*>(c);
    float2 r1 = *reinterpret_cast<const float2*>(c + PW);

    float top = fmaf(wx, r0.y - r0.x, r0.x);
    float bot = fmaf(wx, r1.y - r1.x, r1.x);
    return fmaf(wy, bot - top, top);
}

// ---------------------------------------------------------------------------
// Propagation step over batch group [b0, b0+2), 2 pixels per thread:
//   g_out = wA * (sum_t aff_t * bil(g_in, pos_t) + aff_c * g_in[p]) + ff
// last==1: wA -> (1-m); writes unpadded d_out, skips gS upkeep.
// ---------------------------------------------------------------------------
__global__ void __launch_bounds__(256)
prop_kernel(const float* __restrict__ feat_fix,
            const float* __restrict__ gin,
            const float* __restrict__ gSin,
            float* __restrict__ gout,
            float* __restrict__ gSout,
            float* __restrict__ finalout,
            int last, int b0) {
    int pair = blockIdx.x * blockDim.x + threadIdx.x;
    int base2 = pair * 2;                 // index within the 2-batch group
    if (base2 >= 2 * HWp) return;
    int brel = base2 / HWp;
    int b = b0 + brel;
    int p = base2 - brel * HWp;           // even; WW even => no row wrap
    int gidx = b * HWp + p;

    int y  = p / WW;
    int x0 = p - y * WW;                  // even
    int x1 = x0 + 1;                      // same row always

    const float2* offp = g_off + (size_t)b * 8 * HWp + p;
    const float*  affp = g_aff + (size_t)b * 9 * HWp + p;
    const float*  gb  = gin  + (size_t)b * PHW + (size_t)PADY * PW + PADX;
    const float*  gSb = gSin + (size_t)b * PHW + (size_t)PADY * PW + PADX;

    const int kyv[8] = {-1, -1, -1, 0, 0, 1, 1, 1};
    const int kxv[8] = {-1, 0, 1, -1, 1, -1, 0, 1};

    float acc0 = 0.0f, acc1 = 0.0f;

#pragma unroll
    for (int t = 0; t < 8; t++) {
        float4 o = *reinterpret_cast<const float4*>(offp + (size_t)t * HWp);
        int j = (t < 4) ? t : (t + 1);    // affinity plane index
        float2 a = *reinterpret_cast<const float2*>(affp + (size_t)j * HWp);

        float s0 = bil_pair(gb, gSb, (float)(y + kyv[t]) + o.x,
                                     (float)(x0 + kxv[t]) + o.y);
        float s1 = bil_pair(gb, gSb, (float)(y + kyv[t]) + o.z,
                                     (float)(x1 + kxv[t]) + o.w);
        acc0 = fmaf(a.x, s0, acc0);
        acc1 = fmaf(a.y, s1, acc1);
    }

    // center tap: offset exactly zero -> sample = g[p] (one aligned LDG.64)
    {
        float2 ac = *reinterpret_cast<const float2*>(affp + (size_t)4 * HWp);
        float2 gc = *reinterpret_cast<const float2*>(gb + (size_t)y * PW + x0);
        acc0 = fmaf(ac.x, gc.x, acc0);
        acc1 = fmaf(ac.y, gc.y, acc1);
    }

    float2 ffv = *reinterpret_cast<const float2*>(feat_fix + gidx);
    float2 w;
    if (last) {
        w.x = (ffv.x > 0.0f) ? 0.0f : 1.0f;
        w.y = (ffv.y > 0.0f) ? 0.0f : 1.0f;
    } else {
        w = *reinterpret_cast<const float2*>(g_wA + gidx);
    }

    float r0 = fmaf(w.x, acc0, ffv.x);
    float r1 = fmaf(w.y, acc1, ffv.y);

    if (last) {
        *reinterpret_cast<float2*>(finalout + gidx) = make_float2(r0, r1);
    } else {
        size_t pb = (size_t)b * PHW + (size_t)(y + PADY) * PW + PADX;
        *reinterpret_cast<float2*>(gout + pb + x0) = make_float2(r0, r1);
        // shifted copy upkeep: gS[x0-1]=r0 (odd slot), gS[x0]=r1
        gSout[pb + x0 - 1] = r0;
        gSout[pb + x0]     = r1;
    }
}

// ---------------------------------------------------------------------------
extern "C" void kernel_launch(void* const* d_in, const int* in_sizes, int n_in,
                              void* d_out, int out_size) {
    const float* feat_init  = (const float*)d_in[0];
    const float* guidance   = (const float*)d_in[1];
    const float* confidence = (const float*)d_in[2];
    const float* feat_fix   = (const float*)d_in[3];
    const float* aff_scale  = (const float*)d_in[4];
    float* out = (float*)d_out;

    float *gp = nullptr, *gq = nullptr, *sp = nullptr, *sq = nullptr;
    cudaGetSymbolAddress((void**)&gp, g_pingA);
    cudaGetSymbolAddress((void**)&gq, g_pongA);
    cudaGetSymbolAddress((void**)&sp, gS_pingA);
    cudaGetSymbolAddress((void**)&sq, gS_pongA);

    const int threads = 256;
    const int blocksA = (NPIX + threads - 1) / threads;
    const int blocksP = (2 * HWp / 2 + threads - 1) / threads;   // 1200

    precompute_kernel<<<blocksA, threads>>>(feat_init, guidance, confidence,
                                            feat_fix, aff_scale);

    // Batch groups {0,1} then {2,3}
    for (int b0 = 0; b0 < BB; b0 += 2) {
        float *gcur = gp, *gnxt = gq, *scur = sp, *snxt = sq;
        for (int i = 1; i <= 17; i++) {
            prop_kernel<<<blocksP, threads>>>(feat_fix, gcur, scur,
                                              gnxt, snxt, nullptr,
                                              /*last=*/0, b0);
            float* t;
            t = gcur; gcur = gnxt; gnxt = t;
            t = scur; scur = snxt; snxt = t;
        }
        prop_kernel<<<blocksP, threads>>>(feat_fix, gcur, scur,
                                          nullptr, nullptr, out,
                                          /*last=*/1, b0);
    }
}